// round 7
// baseline (speedup 1.0000x reference)
#include <cuda_runtime.h>
#include <stdint.h>

// Problem constants (fixed: IM_SIZE=(1080,1920), SCALE=(0.25,0.25), B=8, C=3)
#define H_IN 1080
#define W_IN 1920
#define OH   270
#define OW   480
#define BC   24
#define MAX_TAPS 20
#define WQ   (W_IN / 4)

// Scratch: vertical-resized intermediate [BC, OH, W_IN] (~49.8 MB)
__device__ float g_mid[(size_t)BC * OH * W_IN];

// ---------------------------------------------------------------------------
// Pass 1: vertical resample. mid[bc,oh,w] = sum_p w_h[oh,p] * x[bc, idx_h[oh,p], w]
// float4 along W; weights/rows staged in shared once per block.
// grid: (WQ/128, OH, BC), block: 128
// ---------------------------------------------------------------------------
template <int TAPS>
__global__ void __launch_bounds__(128)
pass1_vert(const float* __restrict__ x,
           const float* __restrict__ w_h,
           const int* __restrict__ idx_h,
           int taps_rt)
{
    const int taps = (TAPS > 0) ? TAPS : taps_rt;
    __shared__ float sw[MAX_TAPS];
    __shared__ int   srow[MAX_TAPS];

    const int oh = blockIdx.y;
    const int bc = blockIdx.z;
    const int t  = threadIdx.x;

    if (t < taps) {
        sw[t] = w_h[oh * taps + t];
        int r = idx_h[oh * taps + t];
        r = (r < 0) ? 0 : (r > H_IN - 1 ? H_IN - 1 : r);
        srow[t] = r;
    }
    __syncthreads();

    const int wq = blockIdx.x * 128 + t;
    if (wq >= WQ) return;

    const float4* xin = (const float4*)x + (size_t)bc * H_IN * WQ + wq;

    float4 acc = make_float4(0.f, 0.f, 0.f, 0.f);
#pragma unroll
    for (int p = 0; p < ((TAPS > 0) ? TAPS : MAX_TAPS); ++p) {
        if (TAPS == 0 && p >= taps) break;
        const float  w = sw[p];
        const float4 v = __ldg(xin + (size_t)srow[p] * WQ);
        acc.x += w * v.x; acc.y += w * v.y; acc.z += w * v.z; acc.w += w * v.w;
    }

    ((float4*)g_mid)[((size_t)bc * OH + oh) * WQ + wq] = acc;
}

// ---------------------------------------------------------------------------
// Pass 2: horizontal resample, warp-autonomous.
// Tap indices per output are (mirrored-)contiguous, so a warp's 32 outputs
// touch a contiguous span <= ~150 cols. Each warp stages its own span into a
// private skewed smem segment (coalesced), __syncwarp only, gathers, stores.
// No block barriers. R rows per block amortize weight/idx table loads.
// grid: (1, OH/R, BC), block: 480 (15 independent warps)
// ---------------------------------------------------------------------------
#define R_ROWS2 15
#define SEG     256
#define SEG_SK  (SEG + SEG / 32)   // 264 floats per warp segment
#define NWARPS  15

template <int TAPS>
__global__ void __launch_bounds__(480)
pass2_horiz(const float* __restrict__ w_w,
            const int* __restrict__ idx_w,
            float* __restrict__ out,
            int taps_rt)
{
    const int taps = (TAPS > 0) ? TAPS : taps_rt;
    __shared__ float sseg[NWARPS][SEG_SK];

    const int t    = threadIdx.x;          // == ow (OW == 480)
    const int lane = t & 31;
    const int wi   = t >> 5;
    const int bc   = blockIdx.z;
    const int oh0  = blockIdx.y * R_ROWS2;

    // Per-thread horizontal weights + raw clamped indices
    float wreg[(TAPS > 0) ? TAPS : MAX_TAPS];
    int   creg[(TAPS > 0) ? TAPS : MAX_TAPS];
    int cmin = W_IN, cmax = 0;
#pragma unroll
    for (int p = 0; p < ((TAPS > 0) ? TAPS : MAX_TAPS); ++p) {
        if (TAPS == 0 && p >= taps) break;
        wreg[p] = w_w[t * taps + p];
        int c = idx_w[t * taps + p];
        c = (c < 0) ? 0 : (c > W_IN - 1 ? W_IN - 1 : c);
        creg[p] = c;
        cmin = (c < cmin) ? c : cmin;
        cmax = (c > cmax) ? c : cmax;
    }

    // Warp-reduce span [lo, hi]
#pragma unroll
    for (int off = 16; off >= 1; off >>= 1) {
        int m = __shfl_xor_sync(0xFFFFFFFFu, cmin, off);
        int M = __shfl_xor_sync(0xFFFFFFFFu, cmax, off);
        cmin = (m < cmin) ? m : cmin;
        cmax = (M > cmax) ? M : cmax;
    }
    const int lo   = cmin;
    int span = cmax - lo + 1;
    if (span > SEG) span = SEG;            // structural bound ~150; safety clamp

    // Pre-skewed local positions
    int lp[(TAPS > 0) ? TAPS : MAX_TAPS];
#pragma unroll
    for (int p = 0; p < ((TAPS > 0) ? TAPS : MAX_TAPS); ++p) {
        if (TAPS == 0 && p >= taps) break;
        int rel = creg[p] - lo;
        rel = (rel < 0) ? 0 : (rel > SEG - 1 ? SEG - 1 : rel);
        lp[p] = rel + (rel >> 5);
    }

    float* seg = sseg[wi];

    for (int r = 0; r < R_ROWS2; ++r) {
        const int oh = oh0 + r;
        if (oh >= OH) break;

        const float* row = g_mid + ((size_t)bc * OH + oh) * W_IN + lo;

        // Coalesced stage of this warp's span (~5 iterations)
        for (int i = lane; i < span; i += 32)
            seg[i + (i >> 5)] = __ldg(row + i);
        __syncwarp();

        float acc = 0.f;
#pragma unroll
        for (int p = 0; p < ((TAPS > 0) ? TAPS : MAX_TAPS); ++p) {
            if (TAPS == 0 && p >= taps) break;
            acc += wreg[p] * seg[lp[p]];
        }
        out[((size_t)bc * OH + oh) * OW + t] = acc;
        __syncwarp();                       // protect seg before next stage
    }
}

// ---------------------------------------------------------------------------
// kernel_launch
// inputs: x(f32), w_h(f32), idx_h(i32), w_w(f32), idx_w(i32); output f32
// ---------------------------------------------------------------------------
extern "C" void kernel_launch(void* const* d_in, const int* in_sizes, int n_in,
                              void* d_out, int out_size)
{
    const float* x     = (const float*)d_in[0];
    const float* w_h   = (const float*)d_in[1];
    const int*   idx_h = (const int*)d_in[2];
    const float* w_w   = (const float*)d_in[3];
    const int*   idx_w = (const int*)d_in[4];
    float*       out   = (float*)d_out;

    int taps_h = in_sizes[1] / OH;
    int taps_w = in_sizes[3] / OW;
    if (taps_h > MAX_TAPS) taps_h = MAX_TAPS;
    if (taps_w > MAX_TAPS) taps_w = MAX_TAPS;

    {
        dim3 grid((WQ + 127) / 128, OH, BC);   // (4, 270, 24)
        if (taps_h == 16)
            pass1_vert<16><<<grid, 128>>>(x, w_h, idx_h, taps_h);
        else
            pass1_vert<0><<<grid, 128>>>(x, w_h, idx_h, taps_h);
    }
    {
        dim3 grid(1, (OH + R_ROWS2 - 1) / R_ROWS2, BC); // (1, 18, 24)
        if (taps_w == 16)
            pass2_horiz<16><<<grid, 480>>>(w_w, idx_w, out, taps_w);
        else
            pass2_horiz<0><<<grid, 480>>>(w_w, idx_w, out, taps_w);
    }
}

// round 11
// speedup vs baseline: 1.4750x; 1.4750x over previous
#include <cuda_runtime.h>
#include <stdint.h>

// Problem constants (fixed: IM_SIZE=(1080,1920), SCALE=(0.25,0.25), B=8, C=3)
#define H_IN 1080
#define W_IN 1920
#define OH   270
#define OW   480
#define BC   24
#define MAX_TAPS 20
#define WQ   (W_IN / 4)

// Scratch: vertical-resized intermediate [BC, OH, W_IN] (~49.8 MB)
__device__ float g_mid[(size_t)BC * OH * W_IN];

// ---------------------------------------------------------------------------
// Pass 1: vertical resample. mid[bc,oh,w] = sum_p w_h[oh,p] * x[bc, idx_h[oh,p], w]
// float4 along W; weights/rows staged in shared once per block. (DRAM-bound.)
// grid: (WQ/128, OH, BC), block: 128
// ---------------------------------------------------------------------------
template <int TAPS>
__global__ void __launch_bounds__(128)
pass1_vert(const float* __restrict__ x,
           const float* __restrict__ w_h,
           const int* __restrict__ idx_h,
           int taps_rt)
{
    const int taps = (TAPS > 0) ? TAPS : taps_rt;
    __shared__ float sw[MAX_TAPS];
    __shared__ int   srow[MAX_TAPS];

    const int oh = blockIdx.y;
    const int bc = blockIdx.z;
    const int t  = threadIdx.x;

    if (t < taps) {
        sw[t] = w_h[oh * taps + t];
        int r = idx_h[oh * taps + t];
        r = (r < 0) ? 0 : (r > H_IN - 1 ? H_IN - 1 : r);
        srow[t] = r;
    }
    __syncthreads();

    const int wq = blockIdx.x * 128 + t;
    if (wq >= WQ) return;

    const float4* xin = (const float4*)x + (size_t)bc * H_IN * WQ + wq;

    float4 acc = make_float4(0.f, 0.f, 0.f, 0.f);
#pragma unroll
    for (int p = 0; p < ((TAPS > 0) ? TAPS : MAX_TAPS); ++p) {
        if (TAPS == 0 && p >= taps) break;
        const float  w = sw[p];
        const float4 v = __ldg(xin + (size_t)srow[p] * WQ);
        acc.x += w * v.x; acc.y += w * v.y; acc.z += w * v.z; acc.w += w * v.w;
    }

    ((float4*)g_mid)[((size_t)bc * OH + oh) * WQ + wq] = acc;
}

// ---------------------------------------------------------------------------
// Pass 2: horizontal resample, block-wide staged + software pipelined.
// 480 threads (one ow each). Per row: write prefetched float4 into skewed
// smem buffer (double-buffered), one __syncthreads, prefetch next row into
// registers (latency hidden under gather), gather 16 taps conflict-free,
// coalesced store. Weight/pos tables registerized once per block (R rows).
// grid: (1, OH/R, BC), block: 480
// ---------------------------------------------------------------------------
#define R_ROWS2 9                      // 270 % 9 == 0 -> grid.y = 30, uniform
#define SROW_SZ (W_IN + W_IN / 32)     // 1980 floats, skewed

template <int TAPS>
__global__ void __launch_bounds__(480)
pass2_horiz(const float* __restrict__ w_w,
            const int* __restrict__ idx_w,
            float* __restrict__ out,
            int taps_rt)
{
    const int taps = (TAPS > 0) ? TAPS : taps_rt;
    __shared__ float buf[2][SROW_SZ];

    const int t   = threadIdx.x;       // == ow (OW == 480)
    const int bc  = blockIdx.z;
    const int oh0 = blockIdx.y * R_ROWS2;

    // Registerized per-thread weights + pre-skewed positions
    float wreg[(TAPS > 0) ? TAPS : MAX_TAPS];
    int   preg[(TAPS > 0) ? TAPS : MAX_TAPS];
#pragma unroll
    for (int p = 0; p < ((TAPS > 0) ? TAPS : MAX_TAPS); ++p) {
        if (TAPS == 0 && p >= taps) break;
        wreg[p] = w_w[t * taps + p];
        int c = idx_w[t * taps + p];
        c = (c < 0) ? 0 : (c > W_IN - 1 ? W_IN - 1 : c);
        preg[p] = c + (c >> 5);
    }

    const int c0   = t * 4;
    const int base = c0 + (c0 >> 5);   // 4 floats stay within one 32-group
    const float4* rows = (const float4*)g_mid + ((size_t)bc * OH + oh0) * WQ + t;

    // Prefetch row 0
    float4 v = __ldg(rows);

#pragma unroll
    for (int r = 0; r < R_ROWS2; ++r) {
        float* cur = buf[r & 1];

        cur[base + 0] = v.x;
        cur[base + 1] = v.y;
        cur[base + 2] = v.z;
        cur[base + 3] = v.w;
        __syncthreads();               // stage visible; also fences gathers from r-2

        if (r + 1 < R_ROWS2)           // prefetch next row (latency hidden)
            v = __ldg(rows + (size_t)(r + 1) * WQ);

        float acc0 = 0.f, acc1 = 0.f;  // split chain
#pragma unroll
        for (int p = 0; p < ((TAPS > 0) ? TAPS : MAX_TAPS); p += 2) {
            if (TAPS == 0 && p >= taps) break;
            acc0 += wreg[p] * cur[preg[p]];
            if (TAPS > 0 || p + 1 < taps)
                acc1 += wreg[p + 1] * cur[preg[p + 1]];
        }
        out[((size_t)bc * OH + oh0 + r) * OW + t] = acc0 + acc1;
    }
}

// ---------------------------------------------------------------------------
// kernel_launch
// inputs: x(f32), w_h(f32), idx_h(i32), w_w(f32), idx_w(i32); output f32
// ---------------------------------------------------------------------------
extern "C" void kernel_launch(void* const* d_in, const int* in_sizes, int n_in,
                              void* d_out, int out_size)
{
    const float* x     = (const float*)d_in[0];
    const float* w_h   = (const float*)d_in[1];
    const int*   idx_h = (const int*)d_in[2];
    const float* w_w   = (const float*)d_in[3];
    const int*   idx_w = (const int*)d_in[4];
    float*       out   = (float*)d_out;

    int taps_h = in_sizes[1] / OH;
    int taps_w = in_sizes[3] / OW;
    if (taps_h > MAX_TAPS) taps_h = MAX_TAPS;
    if (taps_w > MAX_TAPS) taps_w = MAX_TAPS;

    {
        dim3 grid((WQ + 127) / 128, OH, BC);   // (4, 270, 24)
        if (taps_h == 16)
            pass1_vert<16><<<grid, 128>>>(x, w_h, idx_h, taps_h);
        else
            pass1_vert<0><<<grid, 128>>>(x, w_h, idx_h, taps_h);
    }
    {
        dim3 grid(1, OH / R_ROWS2, BC);        // (1, 30, 24) = 720 blocks
        if (taps_w == 16)
            pass2_horiz<16><<<grid, 480>>>(w_w, idx_w, out, taps_w);
        else
            pass2_horiz<0><<<grid, 480>>>(w_w, idx_w, out, taps_w);
    }
}